// round 3
// baseline (speedup 1.0000x reference)
#include <cuda_runtime.h>

#define C 128
#define G_SEG 1024
#define MAX_N 1000000

// Scratch (no allocations allowed in kernel_launch)
static __device__ float g_exps[MAX_N];   // e_i = exp(logit_i)  (no max-subtract: logits ~ N(0,1))
static __device__ float g_sum;           // global softmax denominator

// k0: zero pooled output region + reset sum (d_out is poisoned to 0xAA)
__global__ void k_zero(float* __restrict__ pooled) {
    int i = blockIdx.x * blockDim.x + threadIdx.x;
    if (i < G_SEG * C) pooled[i] = 0.0f;
    if (i == 0) g_sum = 0.0f;
}

// k1: e_i = exp(x[i,:].W + b); accumulate global sum.
// Warp per row, float4 per lane — one coalesced 512 MB pass over x.
__global__ void k_expdot(const float* __restrict__ x,
                         const float* __restrict__ W,
                         const float* __restrict__ b, int N) {
    __shared__ float s_w[C];
    for (int i = threadIdx.x; i < C; i += blockDim.x) s_w[i] = W[i];
    __syncthreads();

    const int lane   = threadIdx.x & 31;
    const int warp   = (blockIdx.x * blockDim.x + threadIdx.x) >> 5;
    const int nwarps = (gridDim.x * blockDim.x) >> 5;
    const float4 wv  = reinterpret_cast<const float4*>(s_w)[lane];
    const float  bb  = b[0];

    float lsum = 0.0f;
    for (int i = warp; i < N; i += nwarps) {
        float4 xv = reinterpret_cast<const float4*>(x + (size_t)i * C)[lane];
        float d = xv.x * wv.x + xv.y * wv.y + xv.z * wv.z + xv.w * wv.w;
        #pragma unroll
        for (int o = 16; o; o >>= 1) d += __shfl_xor_sync(0xffffffffu, d, o);
        if (lane == 0) {
            float e = expf(d + bb);
            g_exps[i] = e;
            lsum += e;
        }
    }

    // block reduce of per-warp sums (held by lane 0 of each warp)
    __shared__ float s_red[32];
    if (lane == 0) s_red[threadIdx.x >> 5] = lsum;
    __syncthreads();
    if (threadIdx.x == 0) {
        float s = 0.0f;
        int nw = blockDim.x >> 5;
        for (int w = 0; w < nw; w++) s += s_red[w];
        atomicAdd(&g_sum, s);
    }
}

// k4: pooled[g, c] += (e_i/sum) * x[i, c] over contiguous sorted segments,
// and write alpha_i = e_i/sum to the output.  One block = 128 channel
// threads x ROWS_PER_BLOCK rows; register accumulate, atomicAdd only at
// segment boundaries / chunk edges. batch is int32.
#define ROWS_PER_BLOCK 256
__global__ void __launch_bounds__(128) k_pool(const float* __restrict__ x,
                                              const int* __restrict__ batch,
                                              float* __restrict__ alpha_out,
                                              float* __restrict__ pooled, int N) {
    int start = blockIdx.x * ROWS_PER_BLOCK;
    if (start >= N) return;
    int end = min(N, start + ROWS_PER_BLOCK);
    const int c = threadIdx.x;
    const float inv = 1.0f / g_sum;

    // Produce the alpha output for this chunk (coalesced, 2 elems/thread)
    for (int i = start + c; i < end; i += 128)
        alpha_out[i] = g_exps[i] * inv;

    int cur = batch[start];
    float acc = 0.0f;

    #pragma unroll 4
    for (int i = start; i < end; i++) {
        int g = batch[i];                          // broadcast
        float a  = __ldg(g_exps + i) * inv;        // broadcast
        float xv = __ldg(x + (size_t)i * C + c);   // coalesced 512B/row
        if (g != cur) {
            int gc = min(max(cur, 0), G_SEG - 1);
            atomicAdd(&pooled[gc * C + c], acc);
            acc = 0.0f;
            cur = g;
        }
        acc = fmaf(a, xv, acc);
    }
    int gc = min(max(cur, 0), G_SEG - 1);
    atomicAdd(&pooled[gc * C + c], acc);
}

extern "C" void kernel_launch(void* const* d_in, const int* in_sizes, int n_in,
                              void* d_out, int out_size) {
    // Defensive input mapping by element counts:
    //   x: N*C (largest), W: C, b: 1, batch: N
    const float* x = nullptr;
    const float* W = nullptr;
    const float* b = nullptr;
    const int*   batch = nullptr;
    int N = 0;
    {
        int xi = 0;
        for (int i = 1; i < n_in; i++) if (in_sizes[i] > in_sizes[xi]) xi = i;
        x = (const float*)d_in[xi];
        N = in_sizes[xi] / C;
        for (int i = 0; i < n_in; i++) {
            if (i == xi) continue;
            if (in_sizes[i] == C)      W = (const float*)d_in[i];
            else if (in_sizes[i] == 1) b = (const float*)d_in[i];
            else if (in_sizes[i] == N) batch = (const int*)d_in[i];
        }
    }

    float* pooled = (float*)d_out;             // [G_SEG, C]
    float* alpha  = (float*)d_out + G_SEG * C; // [N]

    // k0: init outputs + sum
    k_zero<<<(G_SEG * C + 255) / 256, 256>>>(pooled);

    // k1: exp(logits) + global sum  (one 512 MB pass over x)
    k_expdot<<<1480, 256>>>(x, W, b, N);

    // k4: alpha write + segment-pooled weighted sum (second 512 MB pass)
    k_pool<<<(N + ROWS_PER_BLOCK - 1) / ROWS_PER_BLOCK, 128>>>(x, batch, alpha, pooled, N);
}

// round 4
// speedup vs baseline: 1.2881x; 1.2881x over previous
#include <cuda_runtime.h>

#define C 128
#define G_SEG 1024
#define MAX_N 1000000
#define RPW 128   // rows per warp (contiguous chunk)

static __device__ float g_exps[MAX_N];   // e_i = exp(logit_i) (unnormalized)
static __device__ float g_sum;           // global softmax denominator

// k0: zero pooled region + reset sum (d_out poisoned to 0xAA; pooled is atomic target)
__global__ void k_zero(float* __restrict__ pooled) {
    int i = blockIdx.x * blockDim.x + threadIdx.x;
    if (i < G_SEG * C) pooled[i] = 0.0f;
    if (i == 0) g_sum = 0.0f;
}

// k_main: single pass over x.
// Per row: d = x_i.W ; e = exp(d+b) ; acc += e * x_i (per-segment, registers);
// flush acc to pooled (unnormalized) at segment boundaries. Also stores e_i
// and accumulates the global sum of e.
__global__ void __launch_bounds__(256) k_main(const float* __restrict__ x,
                                              const float* __restrict__ W,
                                              const float* __restrict__ b,
                                              const int* __restrict__ batch,
                                              float* __restrict__ pooled, int N) {
    const int lane  = threadIdx.x & 31;
    const int gwarp = (blockIdx.x * blockDim.x + threadIdx.x) >> 5;
    const int start = gwarp * RPW;

    float lsum = 0.0f;   // warp-uniform (all lanes hold same e)

    if (start < N) {
        const int end = min(start + RPW, N);
        const float4 wv = __ldg(reinterpret_cast<const float4*>(W) + lane);
        const float  bb = __ldg(b);

        int cur = __ldg(batch + start);
        float4 acc = make_float4(0.f, 0.f, 0.f, 0.f);

        for (int i = start; i < end; i++) {
            float4 xv = __ldg(reinterpret_cast<const float4*>(x) + (size_t)i * 32 + lane);
            int g = __ldg(batch + i);   // broadcast load

            float d = xv.x * wv.x + xv.y * wv.y + xv.z * wv.z + xv.w * wv.w;
            #pragma unroll
            for (int o = 16; o; o >>= 1) d += __shfl_xor_sync(0xffffffffu, d, o);

            float e = __expf(d + bb);   // one MUFU warp-instruction per row
            if (lane == 0) g_exps[i] = e;
            lsum += e;

            if (g != cur) {
                int gc = min(max(cur, 0), G_SEG - 1);
                float* p = pooled + gc * C + lane * 4;
                atomicAdd(p + 0, acc.x);
                atomicAdd(p + 1, acc.y);
                atomicAdd(p + 2, acc.z);
                atomicAdd(p + 3, acc.w);
                acc = make_float4(0.f, 0.f, 0.f, 0.f);
                cur = g;
            }
            acc.x = fmaf(e, xv.x, acc.x);
            acc.y = fmaf(e, xv.y, acc.y);
            acc.z = fmaf(e, xv.z, acc.z);
            acc.w = fmaf(e, xv.w, acc.w);
        }
        {
            int gc = min(max(cur, 0), G_SEG - 1);
            float* p = pooled + gc * C + lane * 4;
            atomicAdd(p + 0, acc.x);
            atomicAdd(p + 1, acc.y);
            atomicAdd(p + 2, acc.z);
            atomicAdd(p + 3, acc.w);
        }
    }

    // block-level reduction of per-warp sums into g_sum
    __shared__ float s_red[8];
    if (lane == 0) s_red[threadIdx.x >> 5] = lsum;
    __syncthreads();
    if (threadIdx.x == 0) {
        float s = 0.0f;
        #pragma unroll
        for (int w = 0; w < 8; w++) s += s_red[w];
        atomicAdd(&g_sum, s);
    }
}

// k_fin: normalize. pooled *= inv ; alpha = e * inv. (~8 MB traffic)
__global__ void k_fin(float* __restrict__ pooled,
                      float* __restrict__ alpha, int N) {
    const float inv = 1.0f / g_sum;
    const int stride = gridDim.x * blockDim.x;
    for (int i = blockIdx.x * blockDim.x + threadIdx.x; i < N; i += stride)
        alpha[i] = g_exps[i] * inv;
    for (int j = blockIdx.x * blockDim.x + threadIdx.x; j < G_SEG * C; j += stride)
        pooled[j] *= inv;
}

extern "C" void kernel_launch(void* const* d_in, const int* in_sizes, int n_in,
                              void* d_out, int out_size) {
    // Defensive input mapping by element counts: x: N*C, W: C, b: 1, batch: N
    const float* x = nullptr;
    const float* W = nullptr;
    const float* b = nullptr;
    const int*   batch = nullptr;
    int N = 0;
    {
        int xi = 0;
        for (int i = 1; i < n_in; i++) if (in_sizes[i] > in_sizes[xi]) xi = i;
        x = (const float*)d_in[xi];
        N = in_sizes[xi] / C;
        for (int i = 0; i < n_in; i++) {
            if (i == xi) continue;
            if (in_sizes[i] == C)      W = (const float*)d_in[i];
            else if (in_sizes[i] == 1) b = (const float*)d_in[i];
            else if (in_sizes[i] == N) batch = (const int*)d_in[i];
        }
    }

    float* pooled = (float*)d_out;             // [G_SEG, C]
    float* alpha  = (float*)d_out + G_SEG * C; // [N]

    k_zero<<<(G_SEG * C + 255) / 256, 256>>>(pooled);

    // single 512 MB pass over x
    int nwarps = (N + RPW - 1) / RPW;
    int nblocks = (nwarps + 7) / 8;           // 8 warps (256 thr) per block
    k_main<<<nblocks, 256>>>(x, W, b, batch, pooled, N);

    // normalize + emit alpha
    k_fin<<<2048, 256>>>(pooled, alpha, N);
}

// round 5
// speedup vs baseline: 2.1751x; 1.6886x over previous
#include <cuda_runtime.h>

#define C 128
#define G_SEG 1024
#define MAX_N 1000000
#define RPW 128   // rows per warp (contiguous chunk, multiple of 4)

static __device__ float g_exps[MAX_N];   // e_i = exp(logit_i) (unnormalized)
static __device__ float g_sum;           // global softmax denominator

// k0: zero pooled region + reset sum (d_out poisoned to 0xAA)
__global__ void k_zero(float* __restrict__ pooled) {
    int i = blockIdx.x * blockDim.x + threadIdx.x;
    if (i < G_SEG * C) pooled[i] = 0.0f;
    if (i == 0) g_sum = 0.0f;
}

__device__ __forceinline__ void flush_acc(float* __restrict__ pooled,
                                          int seg, int lane, float4& acc) {
    int gc = min(max(seg, 0), G_SEG - 1);
    float* p = pooled + gc * C + lane * 4;
    atomicAdd(p + 0, acc.x);
    atomicAdd(p + 1, acc.y);
    atomicAdd(p + 2, acc.z);
    atomicAdd(p + 3, acc.w);
    acc = make_float4(0.f, 0.f, 0.f, 0.f);
}

// k_main: single 512 MB pass over x, 4 rows in flight per warp (ILP/MLP).
__global__ void __launch_bounds__(256) k_main(const float* __restrict__ x,
                                              const float* __restrict__ W,
                                              const float* __restrict__ b,
                                              const int* __restrict__ batch,
                                              float* __restrict__ pooled, int N) {
    const int lane  = threadIdx.x & 31;
    const int gwarp = (blockIdx.x * blockDim.x + threadIdx.x) >> 5;
    const int start = gwarp * RPW;

    float lsum = 0.0f;   // warp-uniform

    if (start < N) {
        const int end = min(start + RPW, N);
        const float4 wv = __ldg(reinterpret_cast<const float4*>(W) + lane);
        const float  bb = __ldg(b);
        const float4* xv4 = reinterpret_cast<const float4*>(x);

        int cur = __ldg(batch + start);
        float4 acc = make_float4(0.f, 0.f, 0.f, 0.f);

        int i = start;
        for (; i + 3 < end; i += 4) {
            // 4 independent loads -> MLP=4 on the big stream
            float4 x0 = __ldg(xv4 + (size_t)(i + 0) * 32 + lane);
            float4 x1 = __ldg(xv4 + (size_t)(i + 1) * 32 + lane);
            float4 x2 = __ldg(xv4 + (size_t)(i + 2) * 32 + lane);
            float4 x3 = __ldg(xv4 + (size_t)(i + 3) * 32 + lane);
            int4   gq = __ldg(reinterpret_cast<const int4*>(batch + i)); // aligned

            float d0 = x0.x*wv.x + x0.y*wv.y + x0.z*wv.z + x0.w*wv.w;
            float d1 = x1.x*wv.x + x1.y*wv.y + x1.z*wv.z + x1.w*wv.w;
            float d2 = x2.x*wv.x + x2.y*wv.y + x2.z*wv.z + x2.w*wv.w;
            float d3 = x3.x*wv.x + x3.y*wv.y + x3.z*wv.z + x3.w*wv.w;

            // interleaved butterflies: 4 independent chains share the latency
            #pragma unroll
            for (int o = 16; o; o >>= 1) {
                d0 += __shfl_xor_sync(0xffffffffu, d0, o);
                d1 += __shfl_xor_sync(0xffffffffu, d1, o);
                d2 += __shfl_xor_sync(0xffffffffu, d2, o);
                d3 += __shfl_xor_sync(0xffffffffu, d3, o);
            }

            float e0 = __expf(d0 + bb);
            float e1 = __expf(d1 + bb);
            float e2 = __expf(d2 + bb);
            float e3 = __expf(d3 + bb);

            if (lane == 0)
                *reinterpret_cast<float4*>(g_exps + i) = make_float4(e0, e1, e2, e3);
            lsum += (e0 + e1) + (e2 + e3);

            // per-row segment boundary handling (sorted batch)
            if (gq.x != cur) flush_acc(pooled, cur, lane, acc), cur = gq.x;
            acc.x = fmaf(e0, x0.x, acc.x); acc.y = fmaf(e0, x0.y, acc.y);
            acc.z = fmaf(e0, x0.z, acc.z); acc.w = fmaf(e0, x0.w, acc.w);

            if (gq.y != cur) flush_acc(pooled, cur, lane, acc), cur = gq.y;
            acc.x = fmaf(e1, x1.x, acc.x); acc.y = fmaf(e1, x1.y, acc.y);
            acc.z = fmaf(e1, x1.z, acc.z); acc.w = fmaf(e1, x1.w, acc.w);

            if (gq.z != cur) flush_acc(pooled, cur, lane, acc), cur = gq.z;
            acc.x = fmaf(e2, x2.x, acc.x); acc.y = fmaf(e2, x2.y, acc.y);
            acc.z = fmaf(e2, x2.z, acc.z); acc.w = fmaf(e2, x2.w, acc.w);

            if (gq.w != cur) flush_acc(pooled, cur, lane, acc), cur = gq.w;
            acc.x = fmaf(e3, x3.x, acc.x); acc.y = fmaf(e3, x3.y, acc.y);
            acc.z = fmaf(e3, x3.z, acc.z); acc.w = fmaf(e3, x3.w, acc.w);
        }

        // generic tail (safety; unused when chunk length % 4 == 0)
        for (; i < end; i++) {
            float4 xv = __ldg(xv4 + (size_t)i * 32 + lane);
            int g = __ldg(batch + i);
            float d = xv.x*wv.x + xv.y*wv.y + xv.z*wv.z + xv.w*wv.w;
            #pragma unroll
            for (int o = 16; o; o >>= 1) d += __shfl_xor_sync(0xffffffffu, d, o);
            float e = __expf(d + bb);
            if (lane == 0) g_exps[i] = e;
            lsum += e;
            if (g != cur) flush_acc(pooled, cur, lane, acc), cur = g;
            acc.x = fmaf(e, xv.x, acc.x); acc.y = fmaf(e, xv.y, acc.y);
            acc.z = fmaf(e, xv.z, acc.z); acc.w = fmaf(e, xv.w, acc.w);
        }

        flush_acc(pooled, cur, lane, acc);
    }

    // block-level reduction of per-warp sums into g_sum
    __shared__ float s_red[8];
    if (lane == 0) s_red[threadIdx.x >> 5] = lsum;
    __syncthreads();
    if (threadIdx.x == 0) {
        float s = 0.0f;
        #pragma unroll
        for (int w = 0; w < 8; w++) s += s_red[w];
        atomicAdd(&g_sum, s);
    }
}

// k_fin: normalize. alpha = e * inv ; pooled *= inv. (~8 MB traffic)
__global__ void k_fin(float* __restrict__ pooled,
                      float* __restrict__ alpha, int N) {
    const float inv = 1.0f / g_sum;
    const int stride = gridDim.x * blockDim.x;
    for (int i = blockIdx.x * blockDim.x + threadIdx.x; i < N; i += stride)
        alpha[i] = g_exps[i] * inv;
    for (int j = blockIdx.x * blockDim.x + threadIdx.x; j < G_SEG * C; j += stride)
        pooled[j] *= inv;
}

extern "C" void kernel_launch(void* const* d_in, const int* in_sizes, int n_in,
                              void* d_out, int out_size) {
    // Defensive input mapping by element counts: x: N*C, W: C, b: 1, batch: N
    const float* x = nullptr;
    const float* W = nullptr;
    const float* b = nullptr;
    const int*   batch = nullptr;
    int N = 0;
    {
        int xi = 0;
        for (int i = 1; i < n_in; i++) if (in_sizes[i] > in_sizes[xi]) xi = i;
        x = (const float*)d_in[xi];
        N = in_sizes[xi] / C;
        for (int i = 0; i < n_in; i++) {
            if (i == xi) continue;
            if (in_sizes[i] == C)      W = (const float*)d_in[i];
            else if (in_sizes[i] == 1) b = (const float*)d_in[i];
            else if (in_sizes[i] == N) batch = (const int*)d_in[i];
        }
    }

    float* pooled = (float*)d_out;             // [G_SEG, C]
    float* alpha  = (float*)d_out + G_SEG * C; // [N]

    k_zero<<<(G_SEG * C + 255) / 256, 256>>>(pooled);

    int nwarps  = (N + RPW - 1) / RPW;
    int nblocks = (nwarps + 7) / 8;            // 8 warps (256 thr) per block
    k_main<<<nblocks, 256>>>(x, W, b, batch, pooled, N);

    k_fin<<<2048, 256>>>(pooled, alpha, N);
}